// round 3
// baseline (speedup 1.0000x reference)
#include <cuda_runtime.h>
#include <cuda_bf16.h>

// NeighborListForTraining: 2000 molecules x 64 atoms, all ordered intra-mol
// pairs (P = 8,064,000). Output layout (float32, concatenated):
//   [0   ,  P) : i_idx
//   [P   , 2P) : j_idx
//   [2P  , 3P) : d_ij  (0 if d > 5)
//   [3P  , 6P) : r_ij  (row-major 3/pair, 0 if d > 5)
//
// Lane-adjacent pair mapping: consecutive lanes handle consecutive pairs ->
// position loads span ~3 cache lines instead of ~12, all stores coalesced.
// (Resubmission of R2 candidate after infra-failed bench.)

#define NPM   64
#define PPM   (NPM * (NPM - 1))   // 4032
#define CUT   5.0f

__global__ __launch_bounds__(256)
void neighborlist_kernel(const float* __restrict__ pos,
                         float* __restrict__ out,
                         int P)
{
    const int base = blockIdx.x * 1024 + threadIdx.x;

    #pragma unroll
    for (int k = 0; k < 4; ++k) {
        const int p = base + k * 256;          // global pair id (always < P)

        const int m  = p / PPM;                // molecule (magic-multiply div)
        const int q  = p - m * PPM;            // pair within molecule
        const int i  = q / 63;                 // source atom (local)
        const int jj = q - i * 63;
        const int j  = jj + (jj >= i ? 1 : 0); // skip diagonal

        const float* __restrict__ mp = pos + m * (NPM * 3);

        const float xi = __ldg(mp + 3 * i + 0);
        const float yi = __ldg(mp + 3 * i + 1);
        const float zi = __ldg(mp + 3 * i + 2);
        const float xj = __ldg(mp + 3 * j + 0);
        const float yj = __ldg(mp + 3 * j + 1);
        const float zj = __ldg(mp + 3 * j + 2);

        const float dx = xj - xi, dy = yj - yi, dz = zj - zi;
        const float r2 = fmaf(dx, dx, fmaf(dy, dy, dz * dz));
        float d;
        asm("sqrt.approx.f32 %0, %1;" : "=f"(d) : "f"(r2));

        const bool in = (d <= CUT);
        const float dv = in ? d  : 0.0f;
        const float rx = in ? dx : 0.0f;
        const float ry = in ? dy : 0.0f;
        const float rz = in ? dz : 0.0f;

        const int atom_base = m * NPM;

        // coalesced scalar stores (1 wavefront each)
        out[p]            = (float)(atom_base + i);
        out[P + p]        = (float)(atom_base + j);
        out[2 * P + p]    = dv;

        // r_ij: stride-3 scalar stores (3 lines each, 9 wavefronts/warp total)
        float* __restrict__ r = out + (size_t)3 * P + (size_t)3 * p;
        r[0] = rx;
        r[1] = ry;
        r[2] = rz;
    }
}

extern "C" void kernel_launch(void* const* d_in, const int* in_sizes, int n_in,
                              void* d_out, int out_size)
{
    const float* pos = (const float*)d_in[0];

    int n_atoms = in_sizes[0] / 3;      // 128000
    int n_mols  = n_atoms / NPM;        // 2000
    int P       = n_mols * PPM;         // 8,064,000

    float* out = (float*)d_out;

    int threads = 256;
    int blocks  = P / (threads * 4);    // 7875, exact
    neighborlist_kernel<<<blocks, threads>>>(pos, out, P);
}

// round 4
// speedup vs baseline: 1.1075x; 1.1075x over previous
#include <cuda_runtime.h>
#include <cuda_bf16.h>

// NeighborListForTraining: 2000 molecules x 64 atoms, P = 8,064,000 ordered
// intra-mol pairs. Output (f32): [0,P) i_idx | [P,2P) j_idx | [2P,3P) d_ij |
// [3P,6P) r_ij (3/pair). d/r zeroed when d > 5.
//
// R3 lesson: kernel is L1-wavefront-bound; must cut loads AND stores together.
// One block per molecule: positions staged in smem (conflict-free LDS, stride
// 3 coprime with 32 banks); r_ij repacked dense via per-warp smem transpose
// so every global store is dense-minimal. ~18 L1/shared wavefronts per 32
// pairs vs 24 (R3) / ~28 (R1).

#define NPM   64
#define PPM   (NPM * (NPM - 1))   // 4032
#define CUT   5.0f
#define TPB   448                 // 14 warps
#define ITERS (PPM / TPB)         // 9
#define NWARP (TPB / 32)          // 14

__global__ __launch_bounds__(TPB)
void neighborlist_kernel(const float* __restrict__ pos,
                         float* __restrict__ out,
                         int P)
{
    __shared__ float sp[NPM * 3];              // molecule positions (768 B)
    __shared__ float stage[NWARP][2][96];      // per-warp r ping-pong staging

    const int m   = blockIdx.x;                // molecule id
    const int tid = threadIdx.x;

    if (tid < NPM * 3)
        sp[tid] = pos[m * (NPM * 3) + tid];
    __syncthreads();

    const int w = tid >> 5;
    const int l = tid & 31;
    const int atom_base = m * NPM;
    const size_t Ps = (size_t)P;

    #pragma unroll
    for (int it = 0; it < ITERS; ++it) {
        const int q  = it * TPB + tid;         // 0..4031, lane-adjacent
        const int i  = q / 63;                 // magic-multiply div
        const int jj = q - i * 63;
        const int j  = jj + (jj >= i ? 1 : 0); // skip diagonal

        // conflict-free smem reads: bank stride 3, gcd(3,32)=1
        const float xi = sp[3 * i + 0];
        const float yi = sp[3 * i + 1];
        const float zi = sp[3 * i + 2];
        const float xj = sp[3 * j + 0];
        const float yj = sp[3 * j + 1];
        const float zj = sp[3 * j + 2];

        const float dx = xj - xi, dy = yj - yi, dz = zj - zi;
        const float r2 = fmaf(dx, dx, fmaf(dy, dy, dz * dz));
        float d;
        asm("sqrt.approx.f32 %0, %1;" : "=f"(d) : "f"(r2));

        const bool in = (d <= CUT);
        const float dv = in ? d  : 0.0f;
        const float rx = in ? dx : 0.0f;
        const float ry = in ? dy : 0.0f;
        const float rz = in ? dz : 0.0f;

        // dense scalar stores (1 wavefront each per warp)
        const int p = m * PPM + q;
        out[p]           = (float)(atom_base + i);
        out[Ps + p]      = (float)(atom_base + j);
        out[2 * Ps + p]  = dv;

        // r_ij: warp-local smem transpose -> dense float4 stores
        float* s = stage[w][it & 1];
        s[3 * l + 0] = rx;                     // conflict-free STS (stride 3)
        s[3 * l + 1] = ry;
        s[3 * l + 2] = rz;
        __syncwarp();
        if (l < 24) {
            const float4 v = reinterpret_cast<const float4*>(s)[l];
            const int pw = m * PPM + it * TPB + w * 32;   // warp's first pair
            float4* rb = reinterpret_cast<float4*>(out + 3 * Ps + (size_t)3 * pw);
            rb[l] = v;                         // 384 B dense, 16B-aligned
        }
    }
}

extern "C" void kernel_launch(void* const* d_in, const int* in_sizes, int n_in,
                              void* d_out, int out_size)
{
    const float* pos = (const float*)d_in[0];

    int n_atoms = in_sizes[0] / 3;      // 128000
    int n_mols  = n_atoms / NPM;        // 2000
    int P       = n_mols * PPM;         // 8,064,000

    float* out = (float*)d_out;

    neighborlist_kernel<<<n_mols, TPB>>>(pos, out, P);
}

// round 5
// speedup vs baseline: 1.1125x; 1.0046x over previous
#include <cuda_runtime.h>
#include <cuda_bf16.h>
#include <cstdint>

// NeighborListForTraining: 2000 molecules x 64 atoms, P = 8,064,000 ordered
// intra-mol pairs. Output (f32): [0,P) i_idx | [P,2P) j_idx | [2P,3P) d_ij |
// [3P,6P) r_ij (3/pair). d/r zeroed when d > 5.
//
// R4 lesson: L1/LSU wavefront slots bind; the smem repack round-trip is 1/3
// of them. This version stages each iteration's outputs in smem ALREADY in
// output order (stride-3 STS is conflict-free, so the transpose is free) and
// lets TMA (cp.async.bulk S2G) do all global stores -> zero STG wavefronts,
// zero repack LDS. 12 LSU wavefronts / 32 pairs vs 18 before.

#define NPM   64
#define PPM   (NPM * (NPM - 1))   // 4032
#define CUT   5.0f
#define TPB   448                 // 14 warps; 4032/448 = 9 iters, exact
#define ITERS (PPM / TPB)

__device__ __forceinline__ uint32_t smem_u32(const void* p) {
    uint32_t a;
    asm("{ .reg .u64 t; cvta.to.shared.u64 t, %1; cvt.u32.u64 %0, t; }"
        : "=r"(a) : "l"(p));
    return a;
}

__device__ __forceinline__ void bulk_s2g(float* g, uint32_t s, uint32_t bytes) {
    asm volatile("cp.async.bulk.global.shared::cta.bulk_group [%0], [%1], %2;"
                 :: "l"(g), "r"(s), "r"(bytes) : "memory");
}

__global__ __launch_bounds__(TPB)
void neighborlist_kernel(const float* __restrict__ pos,
                         float* __restrict__ out,
                         int P)
{
    __shared__ float sp[NPM * 3];                       // molecule positions
    __shared__ __align__(16) float s_i[2][TPB];         // staged i_idx
    __shared__ __align__(16) float s_j[2][TPB];         // staged j_idx
    __shared__ __align__(16) float s_d[2][TPB];         // staged d_ij
    __shared__ __align__(16) float s_r[2][TPB * 3];     // staged r_ij

    const int m   = blockIdx.x;
    const int tid = threadIdx.x;

    if (tid < NPM * 3)
        sp[tid] = pos[m * (NPM * 3) + tid];
    __syncthreads();

    const int atom_base = m * NPM;
    const size_t Ps = (size_t)P;

    #pragma unroll
    for (int it = 0; it < ITERS; ++it) {
        const int b  = it & 1;
        const int q  = it * TPB + tid;          // 0..4031, lane-adjacent
        const int i  = q / 63;                  // magic-multiply div
        const int jj = q - i * 63;
        const int j  = jj + (jj >= i ? 1 : 0);  // skip diagonal

        // conflict-free smem reads (stride 3; i nearly warp-uniform)
        const float xi = sp[3 * i + 0];
        const float yi = sp[3 * i + 1];
        const float zi = sp[3 * i + 2];
        const float xj = sp[3 * j + 0];
        const float yj = sp[3 * j + 1];
        const float zj = sp[3 * j + 2];

        const float dx = xj - xi, dy = yj - yi, dz = zj - zi;
        const float r2 = fmaf(dx, dx, fmaf(dy, dy, dz * dz));
        float d;
        asm("sqrt.approx.f32 %0, %1;" : "=f"(d) : "f"(r2));

        const bool in = (d <= CUT);
        const float dv = in ? d  : 0.0f;
        const float rx = in ? dx : 0.0f;
        const float ry = in ? dy : 0.0f;
        const float rz = in ? dz : 0.0f;

        // release staging buffer b (TMA group issued at it-2 must be done reading)
        if (it >= 2 && tid == 0)
            asm volatile("cp.async.bulk.wait_group.read 1;" ::: "memory");
        __syncthreads();

        // stage in OUTPUT order: all STS conflict-free
        s_i[b][tid]         = (float)(atom_base + i);
        s_j[b][tid]         = (float)(atom_base + j);
        s_d[b][tid]         = dv;
        s_r[b][3 * tid + 0] = rx;               // stride 3, gcd(3,32)=1
        s_r[b][3 * tid + 1] = ry;
        s_r[b][3 * tid + 2] = rz;
        __syncthreads();

        // one thread ships the whole chunk via TMA
        if (tid == 0) {
            asm volatile("fence.proxy.async.shared::cta;" ::: "memory");
            const int p0 = m * PPM + it * TPB;  // chunk's first pair
            bulk_s2g(out + p0,                   smem_u32(s_i[b]), TPB * 4);
            bulk_s2g(out + Ps + p0,              smem_u32(s_j[b]), TPB * 4);
            bulk_s2g(out + 2 * Ps + p0,          smem_u32(s_d[b]), TPB * 4);
            bulk_s2g(out + 3 * Ps + (size_t)3 * p0, smem_u32(s_r[b]), TPB * 12);
            asm volatile("cp.async.bulk.commit_group;" ::: "memory");
        }
    }

    // drain outstanding bulk stores before exit
    if (tid == 0)
        asm volatile("cp.async.bulk.wait_group 0;" ::: "memory");
}

extern "C" void kernel_launch(void* const* d_in, const int* in_sizes, int n_in,
                              void* d_out, int out_size)
{
    const float* pos = (const float*)d_in[0];

    int n_atoms = in_sizes[0] / 3;      // 128000
    int n_mols  = n_atoms / NPM;        // 2000
    int P       = n_mols * PPM;         // 8,064,000

    float* out = (float*)d_out;

    neighborlist_kernel<<<n_mols, TPB>>>(pos, out, P);
}